// round 15
// baseline (speedup 1.0000x reference)
#include <cuda_runtime.h>
#include <cuda_fp16.h>
#include <stdint.h>

// Problem constants
#define Bn  2
#define Sn  2048
#define Dn  1024
#define Hn  16
#define DHn 64
#define BHn (Bn*Hn)
#define CSC 0.18033688f   // 0.125 * log2(e)

// ---------------------------------------------------------------------------
// Scratch — all fp16 planes, including T
// ---------------------------------------------------------------------------
__device__ uint16_t g_Q [(size_t)Bn*Sn*Dn];
__device__ uint16_t g_K [(size_t)Bn*Sn*Dn];
__device__ uint16_t g_V [(size_t)Bn*Sn*Dn];
__device__ uint16_t g_KR[(size_t)Sn*Dn];
__device__ uint16_t g_x [(size_t)Bn*Sn*Dn];
__device__ uint16_t g_p [(size_t)Sn*Dn];
__device__ uint16_t g_Wt[(size_t)5*Dn*Dn];
__device__ uint16_t g_AO[(size_t)Bn*Sn*Dn];
__device__ uint16_t g_T [(size_t)BHn*Sn*Sn];

// ---------------------------------------------------------------------------
// Helpers
// ---------------------------------------------------------------------------
__device__ __forceinline__ uint32_t smem_u32(const void* p) {
    uint32_t a;
    asm("{ .reg .u64 t; cvta.to.shared.u64 t, %1; cvt.u32.u64 %0, t; }"
        : "=r"(a) : "l"(p));
    return a;
}
__device__ __forceinline__ void ldm4(uint32_t addr, uint32_t* r) {
    asm volatile("ldmatrix.sync.aligned.m8n8.x4.shared.b16 {%0,%1,%2,%3}, [%4];"
        : "=r"(r[0]), "=r"(r[1]), "=r"(r[2]), "=r"(r[3]) : "r"(addr));
}
__device__ __forceinline__ void ldm4t(uint32_t addr, uint32_t* r) {
    asm volatile("ldmatrix.sync.aligned.m8n8.x4.trans.shared.b16 {%0,%1,%2,%3}, [%4];"
        : "=r"(r[0]), "=r"(r[1]), "=r"(r[2]), "=r"(r[3]) : "r"(addr));
}
__device__ __forceinline__ void mma_h(float* c, const uint32_t* a, const uint32_t* b) {
    asm volatile(
        "mma.sync.aligned.m16n8k16.row.col.f32.f16.f16.f32 "
        "{%0,%1,%2,%3}, {%4,%5,%6,%7}, {%8,%9}, {%0,%1,%2,%3};"
        : "+f"(c[0]), "+f"(c[1]), "+f"(c[2]), "+f"(c[3])
        : "r"(a[0]), "r"(a[1]), "r"(a[2]), "r"(a[3]), "r"(b[0]), "r"(b[1]));
}
__device__ __forceinline__ float ex2f(float x) {
    float y; asm("ex2.approx.ftz.f32 %0, %1;" : "=f"(y) : "f"(x)); return y;
}
__device__ __forceinline__ uint32_t cvt2h(float x0, float x1) {
    uint32_t w;
    asm("cvt.rn.f16x2.f32 %0, %1, %2;" : "=r"(w) : "f"(x1), "f"(x0));
    return w;
}
__device__ __forceinline__ float2 unpack_h2(uint32_t w) {
    __half2 h = *reinterpret_cast<__half2*>(&w);
    return __half22float2(h);
}
__device__ __forceinline__ void cpa16(uint32_t dst, const void* src) {
    asm volatile("cp.async.cg.shared.global [%0], [%1], 16;" :: "r"(dst), "l"(src));
}
#define CPA_COMMIT()  asm volatile("cp.async.commit_group;" ::: "memory")
#define CPA_WAIT(N)   asm volatile("cp.async.wait_group %0;" :: "n"(N) : "memory")

// ---------------------------------------------------------------------------
// One-time fp16 conversion (merged x + pos into one launch via z)
// ---------------------------------------------------------------------------
__global__ __launch_bounds__(256)
void conv_elem(const float* __restrict__ x, const float* __restrict__ pos)
{
    const int z = blockIdx.y;
    const float* src = z ? pos : x;
    uint16_t* d = z ? g_p : g_x;
    const int n4 = (z ? Sn*Dn : Bn*Sn*Dn) / 4;
    int i = blockIdx.x * 256 + threadIdx.x;
    if (i >= n4) return;
    float4 v = ((const float4*)src)[i];
    ((uint32_t*)d)[i*2]     = cvt2h(v.x, v.y);
    ((uint32_t*)d)[i*2 + 1] = cvt2h(v.z, v.w);
}

__global__ __launch_bounds__(256)
void conv_wt(const float* __restrict__ Wq, const float* __restrict__ Wk,
             const float* __restrict__ Wv, const float* __restrict__ Wkr,
             const float* __restrict__ Wo)
{
    __shared__ float tile[32][33];
    const int z = blockIdx.z;
    const float* W = (z == 0) ? Wq : (z == 1) ? Wk : (z == 2) ? Wv
                   : (z == 3) ? Wkr : Wo;
    uint16_t* o = g_Wt + (size_t)z * Dn * Dn;
    const int k0 = blockIdx.y << 5, n0 = blockIdx.x << 5;
    const int tr = threadIdx.x >> 5, tc = threadIdx.x & 31;
#pragma unroll
    for (int i = 0; i < 4; i++)
        tile[tr + i*8][tc] = W[(size_t)(k0 + tr + i*8) * Dn + n0 + tc];
    __syncthreads();
#pragma unroll
    for (int i = 0; i < 4; i++) {
        int n = tr + i*8;
        __half hv = __float2half_rn(tile[tc][n]);
        o[(size_t)(n0 + n) * Dn + k0 + tc] = *reinterpret_cast<uint16_t*>(&hv);
    }
}

// ---------------------------------------------------------------------------
// fp16 plane GEMM (unchanged from R14 — at HMMA/L1 equilibrium)
// ---------------------------------------------------------------------------
#define SPITCH 40
#define GOA 0
#define GOB 5120
#define GSTAGE_SZ 10240
#define NSTG 5
#define GEMM_SMEM (NSTG*GSTAGE_SZ*2)

__device__ __forceinline__
void gemm_issue(uint32_t stage_b, const uint16_t* A, const uint16_t* B,
                int k0, int row0, int col0, int t)
{
    const int p = t >> 7, r = t & 127;
    const uint16_t* S = (p ? B + (size_t)(col0 + r) * Dn
                           : A + (size_t)(row0 + r) * Dn) + k0;
    uint32_t d = stage_b + (p ? GOB : GOA)*2 + r*80;
#pragma unroll
    for (int i = 0; i < 4; i++)
        cpa16(d + i*16, S + i*8);
}

template<bool PLANE>
__device__ __forceinline__
void gemm_body(const uint16_t* __restrict__ A, const uint16_t* __restrict__ B,
               const float* __restrict__ bias, float* __restrict__ C,
               uint16_t* __restrict__ Cp,
               int row0, int col0, uint16_t* sm)
{
    const int t = threadIdx.x, lane = t & 31, wid = t >> 5;
    const int m0w = (wid & 3) << 5, n0w = (wid >> 2) << 6;
    const int q = lane >> 3, r8 = lane & 7;
    const uint32_t sb = smem_u32(sm);
    const int NC = Dn >> 5;

#pragma unroll
    for (int s = 0; s < 4; s++) {
        gemm_issue(sb + s*GSTAGE_SZ*2, A, B, s*32, row0, col0, t);
        CPA_COMMIT();
    }

    float acc[2][8][4];
#pragma unroll
    for (int mt = 0; mt < 2; mt++)
#pragma unroll
        for (int nt = 0; nt < 8; nt++)
#pragma unroll
            for (int c = 0; c < 4; c++) acc[mt][nt][c] = 0.f;

    for (int c = 0; c < NC; c++) {
        CPA_WAIT(3);
        __syncthreads();
        if (c + 4 < NC)
            gemm_issue(sb + ((c + 4) % NSTG) * GSTAGE_SZ * 2,
                       A, B, (c + 4) * 32, row0, col0, t);
        CPA_COMMIT();

        const uint32_t cb = sb + (c % NSTG) * GSTAGE_SZ * 2;
#pragma unroll
        for (int ks = 0; ks < 2; ks++) {
            uint32_t af[2][4];
#pragma unroll
            for (int mt = 0; mt < 2; mt++) {
                int row = m0w + mt*16 + r8 + (q & 1)*8;
                int col = ks*16 + (q >> 1)*8;
                ldm4(cb + GOA*2 + (uint32_t)(row*SPITCH + col)*2, af[mt]);
            }
            uint32_t bf[8][2];
#pragma unroll
            for (int bt = 0; bt < 4; bt++) {
                int row = n0w + bt*16 + r8 + (q >> 1)*8;
                int col = ks*16 + (q & 1)*8;
                uint32_t tmp[4];
                ldm4(cb + GOB*2 + (uint32_t)(row*SPITCH + col)*2, tmp);
                bf[bt*2][0]=tmp[0]; bf[bt*2][1]=tmp[1];
                bf[bt*2+1][0]=tmp[2]; bf[bt*2+1][1]=tmp[3];
            }
#pragma unroll
            for (int mt = 0; mt < 2; mt++)
#pragma unroll
                for (int nt = 0; nt < 8; nt++)
                    mma_h(acc[mt][nt], af[mt], bf[nt]);
        }
    }

#pragma unroll
    for (int mt = 0; mt < 2; mt++) {
        int m = row0 + m0w + mt*16 + lane/4;
#pragma unroll
        for (int nt = 0; nt < 8; nt++) {
            int n = col0 + n0w + nt*8 + (lane & 3)*2;
            float2 b2 = *(const float2*)(bias + n);
            float v0 = acc[mt][nt][0] + b2.x, v1 = acc[mt][nt][1] + b2.y;
            float v2 = acc[mt][nt][2] + b2.x, v3 = acc[mt][nt][3] + b2.y;
            if (PLANE) {
                *(uint32_t*)&Cp[(size_t)m*Dn + n]     = cvt2h(v0, v1);
                *(uint32_t*)&Cp[(size_t)(m+8)*Dn + n] = cvt2h(v2, v3);
            } else {
                *(float2*)(C + (size_t)m * Dn + n)       = make_float2(v0, v1);
                *(float2*)(C + (size_t)(m + 8) * Dn + n) = make_float2(v2, v3);
            }
        }
    }
}

__global__ __launch_bounds__(256, 2)
void proj_fused(const float* __restrict__ bq, const float* __restrict__ bk,
                const float* __restrict__ bv, const float* __restrict__ bkr)
{
    extern __shared__ uint16_t gsm[];
    const int z = blockIdx.z;
    const int row0 = blockIdx.y << 7, col0 = blockIdx.x << 7;
    if (z == 3 && row0 >= Sn) return;
    const uint16_t* A = (z < 3) ? g_x : g_p;
    const float* bias; uint16_t* Cp;
    if      (z == 0) { bias = bq;  Cp = g_Q;  }
    else if (z == 1) { bias = bk;  Cp = g_K;  }
    else if (z == 2) { bias = bv;  Cp = g_V;  }
    else             { bias = bkr; Cp = g_KR; }
    gemm_body<true>(A, g_Wt + (size_t)z * Dn * Dn, bias, nullptr, Cp,
                    row0, col0, gsm);
}

__global__ __launch_bounds__(256, 2)
void mma_gemm_wo(const float* __restrict__ bias, float* __restrict__ C)
{
    extern __shared__ uint16_t gsm[];
    gemm_body<false>(g_AO, g_Wt + (size_t)4 * Dn * Dn, bias, C, nullptr,
                     blockIdx.y << 7, blockIdx.x << 7, gsm);
}

// ---------------------------------------------------------------------------
// NT GEMM (fp16):  T[bh] = Q_bh [S,64] @ KR_h^T.  fp16 T output.
// ---------------------------------------------------------------------------
#define TP 72
#define TA 0
#define TB (128*TP)
#define TSMEM (2*128*TP*2)

__global__ __launch_bounds__(256, 2)
void mma_gemm_t()
{
    extern __shared__ uint16_t tsm[];
    const int t = threadIdx.x, lane = t & 31, wid = t >> 5;
    const int bh = blockIdx.z, b = bh >> 4, h = bh & 15;
    const int row0 = blockIdx.y << 7, col0 = blockIdx.x << 7;
    const int m0w = (wid & 3) << 5, n0w = (wid >> 2) << 6;
    const int q = lane >> 3, r8 = lane & 7;

    uint16_t* C = g_T + (size_t)bh * Sn * Sn;

    {
        const int r = t >> 1, c = (t & 1) << 5;
        const size_t soA = ((size_t)b*Sn + row0 + r) * Dn + h*DHn + c;
        const size_t soB = ((size_t)col0 + r) * Dn + h*DHn + c;
        const uint32_t sb = smem_u32(tsm);
        uint32_t da = sb + (TA + r*TP + c)*2;
        uint32_t db = sb + (TB + r*TP + c)*2;
#pragma unroll
        for (int i = 0; i < 4; i++) {
            cpa16(da + i*16, g_Q  + soA + i*8);
            cpa16(db + i*16, g_KR + soB + i*8);
        }
        CPA_COMMIT();
        CPA_WAIT(0);
    }
    __syncthreads();

    float acc[2][8][4];
#pragma unroll
    for (int mt = 0; mt < 2; mt++)
#pragma unroll
        for (int nt = 0; nt < 8; nt++)
#pragma unroll
            for (int c = 0; c < 4; c++) acc[mt][nt][c] = 0.f;

    const uint32_t cb = smem_u32(tsm);
#pragma unroll
    for (int ks = 0; ks < 4; ks++) {
        uint32_t af[2][4];
#pragma unroll
        for (int mt = 0; mt < 2; mt++) {
            int row = m0w + mt*16 + r8 + (q & 1)*8;
            int col = ks*16 + (q >> 1)*8;
            ldm4(cb + TA*2 + (uint32_t)(row*TP + col)*2, af[mt]);
        }
        uint32_t bf[8][2];
#pragma unroll
        for (int bt = 0; bt < 4; bt++) {
            int row = n0w + bt*16 + r8 + (q >> 1)*8;
            int col = ks*16 + (q & 1)*8;
            uint32_t tmp[4];
            ldm4(cb + TB*2 + (uint32_t)(row*TP + col)*2, tmp);
            bf[bt*2][0]=tmp[0]; bf[bt*2][1]=tmp[1];
            bf[bt*2+1][0]=tmp[2]; bf[bt*2+1][1]=tmp[3];
        }
#pragma unroll
        for (int mt = 0; mt < 2; mt++)
#pragma unroll
            for (int nt = 0; nt < 8; nt++)
                mma_h(acc[mt][nt], af[mt], bf[nt]);
    }

#pragma unroll
    for (int mt = 0; mt < 2; mt++) {
        int m = row0 + m0w + mt*16 + lane/4;
#pragma unroll
        for (int nt = 0; nt < 8; nt++) {
            int n = col0 + n0w + nt*8 + (lane & 3)*2;
            *(uint32_t*)&C[(size_t)m * Sn + n] =
                cvt2h(acc[mt][nt][0], acc[mt][nt][1]);
            *(uint32_t*)&C[(size_t)(m + 8) * Sn + n] =
                cvt2h(acc[mt][nt][2], acc[mt][nt][3]);
        }
    }
}

// ---------------------------------------------------------------------------
// Flash attention v4: 256 q-rows/block, warp q-tile 32 (2 m-tiles) -> K/V
// fragment traffic per MMA halved. 3-stage cp.async ring, one softmax per
// 64-j tile, fp16 T gather, exp2 softmax. occ 1 (regs ~200).
// ---------------------------------------------------------------------------
#define FP 72
#define FQ 0
#define FSTG0 (256*FP)
#define FSTG_SZ (2*64*FP)
#define FK 0
#define FV (64*FP)
#define FNS 3
#define FLASH_SMEM ((256*FP + FNS*2*64*FP) * 2)   // 92160 bytes

__device__ __forceinline__
void flash_issue(uint32_t base, int s, size_t brow, int j0, int hoff, int t)
{
    const int jr = t >> 2, cb = (t & 3) << 4;
    const size_t so = (brow + j0 + jr) * Dn + hoff + cb;
    const uint32_t st = base + (FSTG0 + s*FSTG_SZ + jr*FP + cb) * 2;
    cpa16(st + FK*2,      g_K + so);  cpa16(st + FK*2 + 16, g_K + so + 8);
    cpa16(st + FV*2,      g_V + so);  cpa16(st + FV*2 + 16, g_V + so + 8);
}

__global__ __launch_bounds__(256, 1)
void flash_mma(const float* __restrict__ u)
{
    extern __shared__ uint16_t fsm[];
    const int t = threadIdx.x, lane = t & 31, w = t >> 5;
    const int q = lane >> 3, r8 = lane & 7;
    const int r = lane >> 2, qq = lane & 3;
    const int bh = blockIdx.y, b = bh >> 4, h = bh & 15;
    const int i0 = blockIdx.x << 8;          // 256 q-rows per block

    const __half* Tg = (const __half*)(g_T + (size_t)bh*Sn*Sn);
    const uint32_t base = smem_u32(fsm);
    const size_t brow = (size_t)b * Sn;
    const int hoff = h * DHn;

    flash_issue(base, 0, brow, 0,  hoff, t);
    CPA_COMMIT();
    flash_issue(base, 1, brow, 64, hoff, t);
    CPA_COMMIT();

    // stage Q: 256 rows, one row per thread: (q + u)*CSC -> fp16
    {
        const size_t so = (brow + i0 + t) * Dn + hoff;
#pragma unroll
        for (int half = 0; half < 2; half++) {
            const int cb = half << 5;
            float uu[32];
#pragma unroll
            for (int i = 0; i < 32; i += 4)
                *(float4*)(uu + i) = *(const float4*)(u + hoff + cb + i);
#pragma unroll
            for (int i = 0; i < 32; i += 8) {
                uint4 hv = *(const uint4*)(g_Q + so + cb + i);
                uint32_t hw[4] = {hv.x, hv.y, hv.z, hv.w};
#pragma unroll
                for (int k = 0; k < 4; k++) {
                    float2 f = unpack_h2(hw[k]);
                    *(uint32_t*)&fsm[FQ + t*FP + cb + i + 2*k] =
                        cvt2h((f.x + uu[i + 2*k]) * CSC,
                              (f.y + uu[i + 2*k + 1]) * CSC);
                }
            }
        }
    }
    __syncthreads();

    // hoisted Q fragments (2 m-tiles of 16 rows)
    uint32_t qf[2][4][4];
#pragma unroll
    for (int mt = 0; mt < 2; mt++)
#pragma unroll
        for (int ks = 0; ks < 4; ks++) {
            int row = w*32 + mt*16 + r8 + (q & 1)*8;
            int col = ks*16 + (q >> 1)*8;
            ldm4(base + FQ*2 + (uint32_t)(row*FP + col)*2, qf[mt][ks]);
        }

    float pacc[2][8][4];
#pragma unroll
    for (int mt = 0; mt < 2; mt++)
#pragma unroll
        for (int dt = 0; dt < 8; dt++)
#pragma unroll
            for (int c = 0; c < 4; c++) pacc[mt][dt][c] = 0.f;
    float mm[2][2] = {{-1e30f, -1e30f}, {-1e30f, -1e30f}};
    float ll[2][2] = {{0.f, 0.f}, {0.f, 0.f}};

    int irow[2][2];
#pragma unroll
    for (int mt = 0; mt < 2; mt++) {
        irow[mt][0] = i0 + w*32 + mt*16 + r;
        irow[mt][1] = irow[mt][0] + 8;
    }

    for (int j0 = 0; j0 < Sn; j0 += 64) {
        const int ti = j0 >> 6;
        CPA_WAIT(1);
        __syncthreads();
        if (j0 + 128 < Sn) flash_issue(base, (ti + 2) % FNS, brow, j0 + 128, hoff, t);
        CPA_COMMIT();

        const uint32_t KB = base + (FSTG0 + (ti % FNS)*FSTG_SZ) * 2;

        // ---- S = Q @ K^T over full tile, both m-tiles (K frags shared)
        float sacc[2][8][4];
#pragma unroll
        for (int mt = 0; mt < 2; mt++)
#pragma unroll
            for (int nt = 0; nt < 8; nt++)
#pragma unroll
                for (int c = 0; c < 4; c++) sacc[mt][nt][c] = 0.f;

#pragma unroll
        for (int ks = 0; ks < 4; ks++) {
            uint32_t kf[8][2];
#pragma unroll
            for (int bt = 0; bt < 4; bt++) {
                int row = bt*16 + r8 + (q >> 1)*8;
                int col = ks*16 + (q & 1)*8;
                uint32_t tmp[4];
                ldm4(KB + FK*2 + (uint32_t)(row*FP + col)*2, tmp);
                kf[bt*2][0]=tmp[0]; kf[bt*2][1]=tmp[1];
                kf[bt*2+1][0]=tmp[2]; kf[bt*2+1][1]=tmp[3];
            }
#pragma unroll
            for (int mt = 0; mt < 2; mt++)
#pragma unroll
                for (int nt = 0; nt < 8; nt++)
                    mma_h(sacc[mt][nt], qf[mt][ks], kf[nt]);
        }

        // ---- add BD (fp16 T gather), per m-tile
#pragma unroll
        for (int mt = 0; mt < 2; mt++)
#pragma unroll
            for (int nt = 0; nt < 8; nt++) {
                int jb = j0 + (nt & 3)*8 + ((nt >> 2) << 5) + 2*qq;
#pragma unroll
                for (int e = 0; e < 4; e++) {
                    int i = irow[mt][e >> 1];
                    int j = jb + (e & 1);
                    int ir = (j <= i) ? i : i + 1;
                    int ic = (j <= i) ? (Sn - 1 - i + j) : (j - i - 2);
                    float v = __half2float(__ldg(Tg + (size_t)ir * Sn + ic));
                    v = (j == i + 1) ? 0.f : v;
                    sacc[mt][nt][e] = fmaf(v, CSC, sacc[mt][nt][e]);
                }
            }
        // NOTE: nt mapping above must match the MMA layout: nt covers j =
        // j0 + nt*8. Fix mapping: recompute with plain nt*8.
#pragma unroll
        for (int mt = 0; mt < 2; mt++) { (void)mt; }

        // ---- ONE online-softmax update per tile, per m-tile
#pragma unroll
        for (int mt = 0; mt < 2; mt++) {
            float ml0 = -1e30f, ml1 = -1e30f;
#pragma unroll
            for (int nt = 0; nt < 8; nt++) {
                ml0 = fmaxf(ml0, fmaxf(sacc[mt][nt][0], sacc[mt][nt][1]));
                ml1 = fmaxf(ml1, fmaxf(sacc[mt][nt][2], sacc[mt][nt][3]));
            }
            ml0 = fmaxf(ml0, __shfl_xor_sync(0xFFFFFFFFu, ml0, 1));
            ml0 = fmaxf(ml0, __shfl_xor_sync(0xFFFFFFFFu, ml0, 2));
            ml1 = fmaxf(ml1, __shfl_xor_sync(0xFFFFFFFFu, ml1, 1));
            ml1 = fmaxf(ml1, __shfl_xor_sync(0xFFFFFFFFu, ml1, 2));

            float mn0 = fmaxf(mm[mt][0], ml0), mn1 = fmaxf(mm[mt][1], ml1);
            float f0 = ex2f(mm[mt][0] - mn0), f1 = ex2f(mm[mt][1] - mn1);
            mm[mt][0] = mn0; mm[mt][1] = mn1;

            float ls0 = 0.f, ls1 = 0.f;
#pragma unroll
            for (int nt = 0; nt < 8; nt++) {
                float p0 = ex2f(sacc[mt][nt][0] - mn0);
                float p1 = ex2f(sacc[mt][nt][1] - mn0);
                float p2 = ex2f(sacc[mt][nt][2] - mn1);
                float p3 = ex2f(sacc[mt][nt][3] - mn1);
                sacc[mt][nt][0] = p0; sacc[mt][nt][1] = p1;
                sacc[mt][nt][2] = p2; sacc[mt][nt][3] = p3;
                ls0 += p0 + p1;  ls1 += p2 + p3;
            }
            ls0 += __shfl_xor_sync(0xFFFFFFFFu, ls0, 1);
            ls0 += __shfl_xor_sync(0xFFFFFFFFu, ls0, 2);
            ls1 += __shfl_xor_sync(0xFFFFFFFFu, ls1, 1);
            ls1 += __shfl_xor_sync(0xFFFFFFFFu, ls1, 2);
            ll[mt][0] = ll[mt][0] * f0 + ls0;
            ll[mt][1] = ll[mt][1] * f1 + ls1;

#pragma unroll
            for (int dt = 0; dt < 8; dt++) {
                pacc[mt][dt][0] *= f0; pacc[mt][dt][1] *= f0;
                pacc[mt][dt][2] *= f1; pacc[mt][dt][3] *= f1;
            }
        }

        // ---- pack P, then PV (V frags shared across m-tiles)
        uint32_t pf[2][4][4];
#pragma unroll
        for (int mt = 0; mt < 2; mt++)
#pragma unroll
            for (int ks = 0; ks < 4; ks++) {
                pf[mt][ks][0] = cvt2h(sacc[mt][2*ks][0],   sacc[mt][2*ks][1]);
                pf[mt][ks][1] = cvt2h(sacc[mt][2*ks][2],   sacc[mt][2*ks][3]);
                pf[mt][ks][2] = cvt2h(sacc[mt][2*ks+1][0], sacc[mt][2*ks+1][1]);
                pf[mt][ks][3] = cvt2h(sacc[mt][2*ks+1][2], sacc[mt][2*ks+1][3]);
            }

#pragma unroll
        for (int ks = 0; ks < 4; ks++) {
            uint32_t vf[8][2];
#pragma unroll
            for (int dt2 = 0; dt2 < 4; dt2++) {
                int krow = ks*16 + (lane & 7) + ((lane >> 3) & 1)*8;
                int ncol = dt2*16 + ((lane >> 4) << 3);
                uint32_t tmp[4];
                ldm4t(KB + FV*2 + (uint32_t)(krow*FP + ncol)*2, tmp);
                vf[dt2*2][0]=tmp[0]; vf[dt2*2][1]=tmp[1];
                vf[dt2*2+1][0]=tmp[2]; vf[dt2*2+1][1]=tmp[3];
            }
#pragma unroll
            for (int mt = 0; mt < 2; mt++)
#pragma unroll
                for (int dt = 0; dt < 8; dt++)
                    mma_h(pacc[mt][dt], pf[mt][ks], vf[dt]);
        }
    }

    // normalize & write AO (fp16 plane)
#pragma unroll
    for (int mt = 0; mt < 2; mt++) {
        float inv0 = 1.f / ll[mt][0], inv1 = 1.f / ll[mt][1];
        const size_t o0 = (brow + irow[mt][0]) * Dn + hoff;
        const size_t o1 = (brow + irow[mt][1]) * Dn + hoff;
#pragma unroll
        for (int dt = 0; dt < 8; dt++) {
            int d = dt*8 + 2*qq;
            *(uint32_t*)&g_AO[o0 + d] = cvt2h(pacc[mt][dt][0]*inv0, pacc[mt][dt][1]*inv0);
            *(uint32_t*)&g_AO[o1 + d] = cvt2h(pacc[mt][dt][2]*inv1, pacc[mt][dt][3]*inv1);
        }
    }
}

// ---------------------------------------------------------------------------
// Launch
// ---------------------------------------------------------------------------
extern "C" void kernel_launch(void* const* d_in, const int* in_sizes, int n_in,
                              void* d_out, int out_size)
{
    const float* x   = (const float*)d_in[0];
    const float* pos = (const float*)d_in[1];
    const float* Wq  = (const float*)d_in[2];
    const float* bq  = (const float*)d_in[3];
    const float* Wk  = (const float*)d_in[4];
    const float* bk  = (const float*)d_in[5];
    const float* Wv  = (const float*)d_in[6];
    const float* bv  = (const float*)d_in[7];
    const float* Wo  = (const float*)d_in[8];
    const float* bo  = (const float*)d_in[9];
    const float* Wkr = (const float*)d_in[10];
    const float* bkr = (const float*)d_in[11];
    const float* u   = (const float*)d_in[12];
    // d_in[13] (v) unused: GH term is per-row constant -> softmax-invariant.

    cudaFuncSetAttribute(proj_fused,  cudaFuncAttributeMaxDynamicSharedMemorySize, GEMM_SMEM);
    cudaFuncSetAttribute(mma_gemm_wo, cudaFuncAttributeMaxDynamicSharedMemorySize, GEMM_SMEM);
    cudaFuncSetAttribute(mma_gemm_t,  cudaFuncAttributeMaxDynamicSharedMemorySize, TSMEM);
    cudaFuncSetAttribute(flash_mma,   cudaFuncAttributeMaxDynamicSharedMemorySize, FLASH_SMEM);
    cudaFuncSetAttribute(flash_mma,   cudaFuncAttributePreferredSharedMemoryCarveout, 100);

    conv_elem<<<dim3((Bn*Sn*Dn/4 + 255)/256, 2), 256>>>(x, pos);
    conv_wt<<<dim3(Dn/32, Dn/32, 5), 256>>>(Wq, Wk, Wv, Wkr, Wo);

    proj_fused<<<dim3(Dn/128, (Bn*Sn)/128, 4), 256, GEMM_SMEM>>>(bq, bk, bv, bkr);
    mma_gemm_t<<<dim3(Sn/128, Sn/128, BHn), 256, TSMEM>>>();
    flash_mma<<<dim3(Sn/256, BHn), 256, FLASH_SMEM>>>(u);
    mma_gemm_wo<<<dim3(Dn/128, (Bn*Sn)/128), 256, GEMM_SMEM>>>(bo, (float*)d_out);
}

// round 16
// speedup vs baseline: 1.2472x; 1.2472x over previous
#include <cuda_runtime.h>
#include <cuda_fp16.h>
#include <stdint.h>

// Problem constants
#define Bn  2
#define Sn  2048
#define Dn  1024
#define Hn  16
#define DHn 64
#define BHn (Bn*Hn)
#define CSC 0.18033688f   // 0.125 * log2(e)

// ---------------------------------------------------------------------------
// Scratch — all fp16 planes, including T
// ---------------------------------------------------------------------------
__device__ uint16_t g_Q [(size_t)Bn*Sn*Dn];
__device__ uint16_t g_K [(size_t)Bn*Sn*Dn];
__device__ uint16_t g_V [(size_t)Bn*Sn*Dn];
__device__ uint16_t g_KR[(size_t)Sn*Dn];
__device__ uint16_t g_x [(size_t)Bn*Sn*Dn];
__device__ uint16_t g_p [(size_t)Sn*Dn];
__device__ uint16_t g_Wt[(size_t)5*Dn*Dn];
__device__ uint16_t g_AO[(size_t)Bn*Sn*Dn];
__device__ uint16_t g_T [(size_t)BHn*Sn*Sn];

// ---------------------------------------------------------------------------
// Helpers
// ---------------------------------------------------------------------------
__device__ __forceinline__ uint32_t smem_u32(const void* p) {
    uint32_t a;
    asm("{ .reg .u64 t; cvta.to.shared.u64 t, %1; cvt.u32.u64 %0, t; }"
        : "=r"(a) : "l"(p));
    return a;
}
__device__ __forceinline__ void ldm4(uint32_t addr, uint32_t* r) {
    asm volatile("ldmatrix.sync.aligned.m8n8.x4.shared.b16 {%0,%1,%2,%3}, [%4];"
        : "=r"(r[0]), "=r"(r[1]), "=r"(r[2]), "=r"(r[3]) : "r"(addr));
}
__device__ __forceinline__ void ldm4t(uint32_t addr, uint32_t* r) {
    asm volatile("ldmatrix.sync.aligned.m8n8.x4.trans.shared.b16 {%0,%1,%2,%3}, [%4];"
        : "=r"(r[0]), "=r"(r[1]), "=r"(r[2]), "=r"(r[3]) : "r"(addr));
}
__device__ __forceinline__ void mma_h(float* c, const uint32_t* a, const uint32_t* b) {
    asm volatile(
        "mma.sync.aligned.m16n8k16.row.col.f32.f16.f16.f32 "
        "{%0,%1,%2,%3}, {%4,%5,%6,%7}, {%8,%9}, {%0,%1,%2,%3};"
        : "+f"(c[0]), "+f"(c[1]), "+f"(c[2]), "+f"(c[3])
        : "r"(a[0]), "r"(a[1]), "r"(a[2]), "r"(a[3]), "r"(b[0]), "r"(b[1]));
}
__device__ __forceinline__ float ex2f(float x) {
    float y; asm("ex2.approx.ftz.f32 %0, %1;" : "=f"(y) : "f"(x)); return y;
}
__device__ __forceinline__ uint32_t cvt2h(float x0, float x1) {
    uint32_t w;
    asm("cvt.rn.f16x2.f32 %0, %1, %2;" : "=r"(w) : "f"(x1), "f"(x0));
    return w;
}
__device__ __forceinline__ float2 unpack_h2(uint32_t w) {
    __half2 h = *reinterpret_cast<__half2*>(&w);
    return __half22float2(h);
}
__device__ __forceinline__ void cpa16(uint32_t dst, const void* src) {
    asm volatile("cp.async.cg.shared.global [%0], [%1], 16;" :: "r"(dst), "l"(src));
}
#define CPA_COMMIT()  asm volatile("cp.async.commit_group;" ::: "memory")
#define CPA_WAIT(N)   asm volatile("cp.async.wait_group %0;" :: "n"(N) : "memory")

// ---------------------------------------------------------------------------
// One-time fp16 conversion (merged x + pos into one launch via y)
// ---------------------------------------------------------------------------
__global__ __launch_bounds__(256)
void conv_elem(const float* __restrict__ x, const float* __restrict__ pos)
{
    const int z = blockIdx.y;
    const float* src = z ? pos : x;
    uint16_t* d = z ? g_p : g_x;
    const int n4 = (z ? Sn*Dn : Bn*Sn*Dn) / 4;
    int i = blockIdx.x * 256 + threadIdx.x;
    if (i >= n4) return;
    float4 v = ((const float4*)src)[i];
    ((uint32_t*)d)[i*2]     = cvt2h(v.x, v.y);
    ((uint32_t*)d)[i*2 + 1] = cvt2h(v.z, v.w);
}

__global__ __launch_bounds__(256)
void conv_wt(const float* __restrict__ Wq, const float* __restrict__ Wk,
             const float* __restrict__ Wv, const float* __restrict__ Wkr,
             const float* __restrict__ Wo)
{
    __shared__ float tile[32][33];
    const int z = blockIdx.z;
    const float* W = (z == 0) ? Wq : (z == 1) ? Wk : (z == 2) ? Wv
                   : (z == 3) ? Wkr : Wo;
    uint16_t* o = g_Wt + (size_t)z * Dn * Dn;
    const int k0 = blockIdx.y << 5, n0 = blockIdx.x << 5;
    const int tr = threadIdx.x >> 5, tc = threadIdx.x & 31;
#pragma unroll
    for (int i = 0; i < 4; i++)
        tile[tr + i*8][tc] = W[(size_t)(k0 + tr + i*8) * Dn + n0 + tc];
    __syncthreads();
#pragma unroll
    for (int i = 0; i < 4; i++) {
        int n = tr + i*8;
        __half hv = __float2half_rn(tile[tc][n]);
        o[(size_t)(n0 + n) * Dn + k0 + tc] = *reinterpret_cast<uint16_t*>(&hv);
    }
}

// ---------------------------------------------------------------------------
// fp16 plane GEMM: 256 thr, 8 warps (32x64), 5-stage cp.async, 2 blocks/SM.
// ---------------------------------------------------------------------------
#define SPITCH 40
#define GOA 0
#define GOB 5120
#define GSTAGE_SZ 10240
#define NSTG 5
#define GEMM_SMEM (NSTG*GSTAGE_SZ*2)

__device__ __forceinline__
void gemm_issue(uint32_t stage_b, const uint16_t* A, const uint16_t* B,
                int k0, int row0, int col0, int t)
{
    const int p = t >> 7, r = t & 127;
    const uint16_t* S = (p ? B + (size_t)(col0 + r) * Dn
                           : A + (size_t)(row0 + r) * Dn) + k0;
    uint32_t d = stage_b + (p ? GOB : GOA)*2 + r*80;
#pragma unroll
    for (int i = 0; i < 4; i++)
        cpa16(d + i*16, S + i*8);
}

template<bool PLANE>
__device__ __forceinline__
void gemm_body(const uint16_t* __restrict__ A, const uint16_t* __restrict__ B,
               const float* __restrict__ bias, float* __restrict__ C,
               uint16_t* __restrict__ Cp,
               int row0, int col0, uint16_t* sm)
{
    const int t = threadIdx.x, lane = t & 31, wid = t >> 5;
    const int m0w = (wid & 3) << 5, n0w = (wid >> 2) << 6;
    const int q = lane >> 3, r8 = lane & 7;
    const uint32_t sb = smem_u32(sm);
    const int NC = Dn >> 5;

#pragma unroll
    for (int s = 0; s < 4; s++) {
        gemm_issue(sb + s*GSTAGE_SZ*2, A, B, s*32, row0, col0, t);
        CPA_COMMIT();
    }

    float acc[2][8][4];
#pragma unroll
    for (int mt = 0; mt < 2; mt++)
#pragma unroll
        for (int nt = 0; nt < 8; nt++)
#pragma unroll
            for (int c = 0; c < 4; c++) acc[mt][nt][c] = 0.f;

    for (int c = 0; c < NC; c++) {
        CPA_WAIT(3);
        __syncthreads();
        if (c + 4 < NC)
            gemm_issue(sb + ((c + 4) % NSTG) * GSTAGE_SZ * 2,
                       A, B, (c + 4) * 32, row0, col0, t);
        CPA_COMMIT();

        const uint32_t cb = sb + (c % NSTG) * GSTAGE_SZ * 2;
#pragma unroll
        for (int ks = 0; ks < 2; ks++) {
            uint32_t af[2][4];
#pragma unroll
            for (int mt = 0; mt < 2; mt++) {
                int row = m0w + mt*16 + r8 + (q & 1)*8;
                int col = ks*16 + (q >> 1)*8;
                ldm4(cb + GOA*2 + (uint32_t)(row*SPITCH + col)*2, af[mt]);
            }
            uint32_t bf[8][2];
#pragma unroll
            for (int bt = 0; bt < 4; bt++) {
                int row = n0w + bt*16 + r8 + (q >> 1)*8;
                int col = ks*16 + (q & 1)*8;
                uint32_t tmp[4];
                ldm4(cb + GOB*2 + (uint32_t)(row*SPITCH + col)*2, tmp);
                bf[bt*2][0]=tmp[0]; bf[bt*2][1]=tmp[1];
                bf[bt*2+1][0]=tmp[2]; bf[bt*2+1][1]=tmp[3];
            }
#pragma unroll
            for (int mt = 0; mt < 2; mt++)
#pragma unroll
                for (int nt = 0; nt < 8; nt++)
                    mma_h(acc[mt][nt], af[mt], bf[nt]);
        }
    }

#pragma unroll
    for (int mt = 0; mt < 2; mt++) {
        int m = row0 + m0w + mt*16 + lane/4;
#pragma unroll
        for (int nt = 0; nt < 8; nt++) {
            int n = col0 + n0w + nt*8 + (lane & 3)*2;
            float2 b2 = *(const float2*)(bias + n);
            float v0 = acc[mt][nt][0] + b2.x, v1 = acc[mt][nt][1] + b2.y;
            float v2 = acc[mt][nt][2] + b2.x, v3 = acc[mt][nt][3] + b2.y;
            if (PLANE) {
                *(uint32_t*)&Cp[(size_t)m*Dn + n]     = cvt2h(v0, v1);
                *(uint32_t*)&Cp[(size_t)(m+8)*Dn + n] = cvt2h(v2, v3);
            } else {
                *(float2*)(C + (size_t)m * Dn + n)       = make_float2(v0, v1);
                *(float2*)(C + (size_t)(m + 8) * Dn + n) = make_float2(v2, v3);
            }
        }
    }
}

__global__ __launch_bounds__(256, 2)
void proj_fused(const float* __restrict__ bq, const float* __restrict__ bk,
                const float* __restrict__ bv, const float* __restrict__ bkr)
{
    extern __shared__ uint16_t gsm[];
    const int z = blockIdx.z;
    const int row0 = blockIdx.y << 7, col0 = blockIdx.x << 7;
    if (z == 3 && row0 >= Sn) return;
    const uint16_t* A = (z < 3) ? g_x : g_p;
    const float* bias; uint16_t* Cp;
    if      (z == 0) { bias = bq;  Cp = g_Q;  }
    else if (z == 1) { bias = bk;  Cp = g_K;  }
    else if (z == 2) { bias = bv;  Cp = g_V;  }
    else             { bias = bkr; Cp = g_KR; }
    gemm_body<true>(A, g_Wt + (size_t)z * Dn * Dn, bias, nullptr, Cp,
                    row0, col0, gsm);
}

__global__ __launch_bounds__(256, 2)
void mma_gemm_wo(const float* __restrict__ bias, float* __restrict__ C)
{
    extern __shared__ uint16_t gsm[];
    gemm_body<false>(g_AO, g_Wt + (size_t)4 * Dn * Dn, bias, C, nullptr,
                     blockIdx.y << 7, blockIdx.x << 7, gsm);
}

// ---------------------------------------------------------------------------
// NT GEMM (fp16):  T[bh] = Q_bh [S,64] @ KR_h^T.  fp16 T output.
// ---------------------------------------------------------------------------
#define TP 72
#define TA 0
#define TB (128*TP)
#define TSMEM (2*128*TP*2)

__global__ __launch_bounds__(256, 2)
void mma_gemm_t()
{
    extern __shared__ uint16_t tsm[];
    const int t = threadIdx.x, lane = t & 31, wid = t >> 5;
    const int bh = blockIdx.z, b = bh >> 4, h = bh & 15;
    const int row0 = blockIdx.y << 7, col0 = blockIdx.x << 7;
    const int m0w = (wid & 3) << 5, n0w = (wid >> 2) << 6;
    const int q = lane >> 3, r8 = lane & 7;

    uint16_t* C = g_T + (size_t)bh * Sn * Sn;

    {
        const int r = t >> 1, c = (t & 1) << 5;
        const size_t soA = ((size_t)b*Sn + row0 + r) * Dn + h*DHn + c;
        const size_t soB = ((size_t)col0 + r) * Dn + h*DHn + c;
        const uint32_t sb = smem_u32(tsm);
        uint32_t da = sb + (TA + r*TP + c)*2;
        uint32_t db = sb + (TB + r*TP + c)*2;
#pragma unroll
        for (int i = 0; i < 4; i++) {
            cpa16(da + i*16, g_Q  + soA + i*8);
            cpa16(db + i*16, g_KR + soB + i*8);
        }
        CPA_COMMIT();
        CPA_WAIT(0);
    }
    __syncthreads();

    float acc[2][8][4];
#pragma unroll
    for (int mt = 0; mt < 2; mt++)
#pragma unroll
        for (int nt = 0; nt < 8; nt++)
#pragma unroll
            for (int c = 0; c < 4; c++) acc[mt][nt][c] = 0.f;

    const uint32_t cb = smem_u32(tsm);
#pragma unroll
    for (int ks = 0; ks < 4; ks++) {
        uint32_t af[2][4];
#pragma unroll
        for (int mt = 0; mt < 2; mt++) {
            int row = m0w + mt*16 + r8 + (q & 1)*8;
            int col = ks*16 + (q >> 1)*8;
            ldm4(cb + TA*2 + (uint32_t)(row*TP + col)*2, af[mt]);
        }
        uint32_t bf[8][2];
#pragma unroll
        for (int bt = 0; bt < 4; bt++) {
            int row = n0w + bt*16 + r8 + (q >> 1)*8;
            int col = ks*16 + (q & 1)*8;
            uint32_t tmp[4];
            ldm4(cb + TB*2 + (uint32_t)(row*TP + col)*2, tmp);
            bf[bt*2][0]=tmp[0]; bf[bt*2][1]=tmp[1];
            bf[bt*2+1][0]=tmp[2]; bf[bt*2+1][1]=tmp[3];
        }
#pragma unroll
        for (int mt = 0; mt < 2; mt++)
#pragma unroll
            for (int nt = 0; nt < 8; nt++)
                mma_h(acc[mt][nt], af[mt], bf[nt]);
    }

#pragma unroll
    for (int mt = 0; mt < 2; mt++) {
        int m = row0 + m0w + mt*16 + lane/4;
#pragma unroll
        for (int nt = 0; nt < 8; nt++) {
            int n = col0 + n0w + nt*8 + (lane & 3)*2;
            *(uint32_t*)&C[(size_t)m * Sn + n] =
                cvt2h(acc[mt][nt][0], acc[mt][nt][1]);
            *(uint32_t*)&C[(size_t)(m + 8) * Sn + n] =
                cvt2h(acc[mt][nt][2], acc[mt][nt][3]);
        }
    }
}

// ---------------------------------------------------------------------------
// Flash attention (R14 exact): 128 q-rows/block, 3-stage cp.async ring,
// one softmax per 64-j tile, fp16 T gather, exp2 softmax, 2 blocks/SM.
// ---------------------------------------------------------------------------
#define FP 72
#define FQ 0
#define FSTG0 (128*FP)
#define FSTG_SZ (2*64*FP)
#define FK 0
#define FV (64*FP)
#define FNS 3
#define FLASH_SMEM ((128*FP + FNS*2*64*FP) * 2)

__device__ __forceinline__
void flash_issue(uint32_t base, int s, size_t brow, int j0, int hoff, int t)
{
    const int jr = t >> 2, cb = (t & 3) << 4;
    const size_t so = (brow + j0 + jr) * Dn + hoff + cb;
    const uint32_t st = base + (FSTG0 + s*FSTG_SZ + jr*FP + cb) * 2;
    cpa16(st + FK*2,      g_K + so);  cpa16(st + FK*2 + 16, g_K + so + 8);
    cpa16(st + FV*2,      g_V + so);  cpa16(st + FV*2 + 16, g_V + so + 8);
}

__global__ __launch_bounds__(256, 2)
void flash_mma(const float* __restrict__ u)
{
    extern __shared__ uint16_t fsm[];
    const int t = threadIdx.x, lane = t & 31, w = t >> 5;
    const int q = lane >> 3, r8 = lane & 7;
    const int r = lane >> 2, qq = lane & 3;
    const int bh = blockIdx.y, b = bh >> 4, h = bh & 15;
    const int i0 = blockIdx.x << 7;

    const __half* Tg = (const __half*)(g_T + (size_t)bh*Sn*Sn);
    const uint32_t base = smem_u32(fsm);
    const size_t brow = (size_t)b * Sn;
    const int hoff = h * DHn;

    flash_issue(base, 0, brow, 0,  hoff, t);
    CPA_COMMIT();
    flash_issue(base, 1, brow, 64, hoff, t);
    CPA_COMMIT();

    // stage Q: (q + u)*CSC -> fp16
    {
        const int qr = t >> 1, cb = (t & 1) << 5;
        const size_t so = (brow + i0 + qr) * Dn + hoff + cb;
        float uu[32];
#pragma unroll
        for (int i = 0; i < 32; i += 4)
            *(float4*)(uu + i) = *(const float4*)(u + hoff + cb + i);
#pragma unroll
        for (int i = 0; i < 32; i += 8) {
            uint4 hv = *(const uint4*)(g_Q + so + i);
            uint32_t hw[4] = {hv.x, hv.y, hv.z, hv.w};
#pragma unroll
            for (int k = 0; k < 4; k++) {
                float2 f = unpack_h2(hw[k]);
                *(uint32_t*)&fsm[FQ + qr*FP + cb + i + 2*k] =
                    cvt2h((f.x + uu[i + 2*k]) * CSC, (f.y + uu[i + 2*k + 1]) * CSC);
            }
        }
    }
    __syncthreads();

    // hoisted Q fragments
    uint32_t qf[4][4];
#pragma unroll
    for (int ks = 0; ks < 4; ks++) {
        int row = w*16 + r8 + (q & 1)*8;
        int col = ks*16 + (q >> 1)*8;
        ldm4(base + FQ*2 + (uint32_t)(row*FP + col)*2, qf[ks]);
    }

    float pacc[8][4];
#pragma unroll
    for (int dt = 0; dt < 8; dt++)
#pragma unroll
        for (int c = 0; c < 4; c++) pacc[dt][c] = 0.f;
    float m0 = -1e30f, m1 = -1e30f, l0 = 0.f, l1 = 0.f;

    const int i_r  = i0 + w*16 + r;
    const int i_r8 = i_r + 8;

    for (int j0 = 0; j0 < Sn; j0 += 64) {
        const int ti = j0 >> 6;
        CPA_WAIT(1);
        __syncthreads();
        if (j0 + 128 < Sn) flash_issue(base, (ti + 2) % FNS, brow, j0 + 128, hoff, t);
        CPA_COMMIT();

        const uint32_t KB = base + (FSTG0 + (ti % FNS)*FSTG_SZ) * 2;

        // ---- BD first half prefetch (fp16, overlaps S-MMAs)
        float bdA[4][4];
#pragma unroll
        for (int nt = 0; nt < 4; nt++) {
            int jb = j0 + nt*8 + 2*qq;
#pragma unroll
            for (int e = 0; e < 4; e++) {
                int i = (e < 2) ? i_r : i_r8;
                int j = jb + (e & 1);
                int ir = (j <= i) ? i : i + 1;
                int ic = (j <= i) ? (Sn - 1 - i + j) : (j - i - 2);
                float v = __half2float(__ldg(Tg + (size_t)ir * Sn + ic));
                bdA[nt][e] = (j == i + 1) ? 0.f : v;
            }
        }

        // ---- S = Q @ K^T over the FULL 64-j tile
        float sacc[8][4];
#pragma unroll
        for (int nt = 0; nt < 8; nt++)
#pragma unroll
            for (int c = 0; c < 4; c++) sacc[nt][c] = 0.f;

#pragma unroll
        for (int ks = 0; ks < 4; ks++) {
            uint32_t kf[8][2];
#pragma unroll
            for (int bt = 0; bt < 4; bt++) {
                int row = bt*16 + r8 + (q >> 1)*8;
                int col = ks*16 + (q & 1)*8;
                uint32_t tmp[4];
                ldm4(KB + FK*2 + (uint32_t)(row*FP + col)*2, tmp);
                kf[bt*2][0]=tmp[0]; kf[bt*2][1]=tmp[1];
                kf[bt*2+1][0]=tmp[2]; kf[bt*2+1][1]=tmp[3];
            }
#pragma unroll
            for (int nt = 0; nt < 8; nt++)
                mma_h(sacc[nt], qf[ks], kf[nt]);
        }

        // ---- add BD first half, then load+add second half
#pragma unroll
        for (int nt = 0; nt < 4; nt++)
#pragma unroll
            for (int e = 0; e < 4; e++)
                sacc[nt][e] = fmaf(bdA[nt][e], CSC, sacc[nt][e]);
#pragma unroll
        for (int nt = 0; nt < 4; nt++) {
            int jb = j0 + 32 + nt*8 + 2*qq;
#pragma unroll
            for (int e = 0; e < 4; e++) {
                int i = (e < 2) ? i_r : i_r8;
                int j = jb + (e & 1);
                int ir = (j <= i) ? i : i + 1;
                int ic = (j <= i) ? (Sn - 1 - i + j) : (j - i - 2);
                float v = __half2float(__ldg(Tg + (size_t)ir * Sn + ic));
                v = (j == i + 1) ? 0.f : v;
                sacc[4 + nt][e] = fmaf(v, CSC, sacc[4 + nt][e]);
            }
        }

        // ---- ONE online-softmax update per 64-j tile
        float ml0 = -1e30f, ml1 = -1e30f;
#pragma unroll
        for (int nt = 0; nt < 8; nt++) {
            ml0 = fmaxf(ml0, fmaxf(sacc[nt][0], sacc[nt][1]));
            ml1 = fmaxf(ml1, fmaxf(sacc[nt][2], sacc[nt][3]));
        }
        ml0 = fmaxf(ml0, __shfl_xor_sync(0xFFFFFFFFu, ml0, 1));
        ml0 = fmaxf(ml0, __shfl_xor_sync(0xFFFFFFFFu, ml0, 2));
        ml1 = fmaxf(ml1, __shfl_xor_sync(0xFFFFFFFFu, ml1, 1));
        ml1 = fmaxf(ml1, __shfl_xor_sync(0xFFFFFFFFu, ml1, 2));

        float mn0 = fmaxf(m0, ml0), mn1 = fmaxf(m1, ml1);
        float f0 = ex2f(m0 - mn0), f1 = ex2f(m1 - mn1);
        m0 = mn0; m1 = mn1;

        float ls0 = 0.f, ls1 = 0.f;
#pragma unroll
        for (int nt = 0; nt < 8; nt++) {
            float p0 = ex2f(sacc[nt][0] - m0);
            float p1 = ex2f(sacc[nt][1] - m0);
            float p2 = ex2f(sacc[nt][2] - m1);
            float p3 = ex2f(sacc[nt][3] - m1);
            sacc[nt][0] = p0; sacc[nt][1] = p1; sacc[nt][2] = p2; sacc[nt][3] = p3;
            ls0 += p0 + p1;  ls1 += p2 + p3;
        }
        ls0 += __shfl_xor_sync(0xFFFFFFFFu, ls0, 1);
        ls0 += __shfl_xor_sync(0xFFFFFFFFu, ls0, 2);
        ls1 += __shfl_xor_sync(0xFFFFFFFFu, ls1, 1);
        ls1 += __shfl_xor_sync(0xFFFFFFFFu, ls1, 2);
        l0 = l0 * f0 + ls0;
        l1 = l1 * f1 + ls1;

#pragma unroll
        for (int dt = 0; dt < 8; dt++) {
            pacc[dt][0] *= f0; pacc[dt][1] *= f0;
            pacc[dt][2] *= f1; pacc[dt][3] *= f1;
        }

        // ---- pack P (C-frag pair -> A-frag), fp16
        uint32_t pf[4][4];
#pragma unroll
        for (int ks = 0; ks < 4; ks++) {
            pf[ks][0] = cvt2h(sacc[2*ks][0],   sacc[2*ks][1]);
            pf[ks][1] = cvt2h(sacc[2*ks][2],   sacc[2*ks][3]);
            pf[ks][2] = cvt2h(sacc[2*ks+1][0], sacc[2*ks+1][1]);
            pf[ks][3] = cvt2h(sacc[2*ks+1][2], sacc[2*ks+1][3]);
        }

        // ---- pacc += P @ V over the full tile
#pragma unroll
        for (int ks = 0; ks < 4; ks++) {
            uint32_t vf[8][2];
#pragma unroll
            for (int dt2 = 0; dt2 < 4; dt2++) {
                int krow = ks*16 + (lane & 7) + ((lane >> 3) & 1)*8;
                int ncol = dt2*16 + ((lane >> 4) << 3);
                uint32_t tmp[4];
                ldm4t(KB + FV*2 + (uint32_t)(krow*FP + ncol)*2, tmp);
                vf[dt2*2][0]=tmp[0]; vf[dt2*2][1]=tmp[1];
                vf[dt2*2+1][0]=tmp[2]; vf[dt2*2+1][1]=tmp[3];
            }
#pragma unroll
            for (int dt = 0; dt < 8; dt++)
                mma_h(pacc[dt], pf[ks], vf[dt]);
        }
    }

    // normalize & write AO (fp16 plane)
    float inv0 = 1.f / l0, inv1 = 1.f / l1;
    const size_t o_r  = (brow + i_r)  * Dn + hoff;
    const size_t o_r8 = (brow + i_r8) * Dn + hoff;
#pragma unroll
    for (int dt = 0; dt < 8; dt++) {
        int d = dt*8 + 2*qq;
        *(uint32_t*)&g_AO[o_r + d]  = cvt2h(pacc[dt][0]*inv0, pacc[dt][1]*inv0);
        *(uint32_t*)&g_AO[o_r8 + d] = cvt2h(pacc[dt][2]*inv1, pacc[dt][3]*inv1);
    }
}

// ---------------------------------------------------------------------------
// Launch
// ---------------------------------------------------------------------------
extern "C" void kernel_launch(void* const* d_in, const int* in_sizes, int n_in,
                              void* d_out, int out_size)
{
    const float* x   = (const float*)d_in[0];
    const float* pos = (const float*)d_in[1];
    const float* Wq  = (const float*)d_in[2];
    const float* bq  = (const float*)d_in[3];
    const float* Wk  = (const float*)d_in[4];
    const float* bk  = (const float*)d_in[5];
    const float* Wv  = (const float*)d_in[6];
    const float* bv  = (const float*)d_in[7];
    const float* Wo  = (const float*)d_in[8];
    const float* bo  = (const float*)d_in[9];
    const float* Wkr = (const float*)d_in[10];
    const float* bkr = (const float*)d_in[11];
    const float* u   = (const float*)d_in[12];
    // d_in[13] (v) unused: GH term is per-row constant -> softmax-invariant.

    cudaFuncSetAttribute(proj_fused,  cudaFuncAttributeMaxDynamicSharedMemorySize, GEMM_SMEM);
    cudaFuncSetAttribute(mma_gemm_wo, cudaFuncAttributeMaxDynamicSharedMemorySize, GEMM_SMEM);
    cudaFuncSetAttribute(mma_gemm_t,  cudaFuncAttributeMaxDynamicSharedMemorySize, TSMEM);
    cudaFuncSetAttribute(flash_mma,   cudaFuncAttributeMaxDynamicSharedMemorySize, FLASH_SMEM);
    cudaFuncSetAttribute(flash_mma,   cudaFuncAttributePreferredSharedMemoryCarveout, 100);

    conv_elem<<<dim3((Bn*Sn*Dn/4 + 255)/256, 2), 256>>>(x, pos);
    conv_wt<<<dim3(Dn/32, Dn/32, 5), 256>>>(Wq, Wk, Wv, Wkr, Wo);

    proj_fused<<<dim3(Dn/128, (Bn*Sn)/128, 4), 256, GEMM_SMEM>>>(bq, bk, bv, bkr);
    mma_gemm_t<<<dim3(Sn/128, Sn/128, BHn), 256, TSMEM>>>();
    flash_mma<<<dim3(Sn/128, BHn), 256, FLASH_SMEM>>>(u);
    mma_gemm_wo<<<dim3(Dn/128, (Bn*Sn)/128), 256, GEMM_SMEM>>>(bo, (float*)d_out);
}